// round 13
// baseline (speedup 1.0000x reference)
#include <cuda_runtime.h>
#include <cuda_bf16.h>
#include <cstdio>

#define FULLMASK 0xffffffffu
#define NG_CAP 50000
#define NI_CAP 100000
#define E_CAP  2000000
#define RS1 68     // smem row stride (u32 words) K=128 tiles
#define RS2 132    // smem row stride (u32 words) K=256 tiles

// ---------------- scratch (device globals) ----------------
__device__ __nv_bfloat16 b_fi   [NI_CAP * 128]; // final_item
__device__ __nv_bfloat16 b_fg   [NG_CAP * 128]; // fus_group
__device__ __nv_bfloat16 b_gfi  [NG_CAP * 128]; // sigmoid(spmm(gi, fi))
__device__ __nv_bfloat16 b_first[NG_CAP * 128]; // first
__device__ __nv_bfloat16 b_fgrp [NG_CAP * 128]; // final_group
__device__ int      g_rp_gi[NG_CAP + 1];
__device__ int      g_rp_gg[NG_CAP + 1];
__device__ unsigned g_off_gi[E_CAP];            // gi_cols * 256 (byte offsets)
__device__ unsigned g_off_gg[E_CAP];            // gg_cols * 256

// ---------------- helpers ----------------
__device__ __forceinline__ float wredsum(float v) {
    #pragma unroll
    for (int o = 16; o; o >>= 1) v += __shfl_xor_sync(FULLMASK, v, o);
    return v;
}
__device__ __forceinline__ float sigf(float x) { return 1.0f / (1.0f + __expf(-x)); }
__device__ __forceinline__ void fma4(float4& a, const float4 w, const float x) {
    a.x = fmaf(w.x, x, a.x); a.y = fmaf(w.y, x, a.y);
    a.z = fmaf(w.z, x, a.z); a.w = fmaf(w.w, x, a.w);
}
__device__ __forceinline__ float4 inorm4(float4 v) {
    float s = v.x + v.y + v.z + v.w;
    float q = v.x*v.x + v.y*v.y + v.z*v.z + v.w*v.w;
    #pragma unroll
    for (int o = 16; o; o >>= 1) {
        s += __shfl_xor_sync(FULLMASK, s, o);
        q += __shfl_xor_sync(FULLMASK, q, o);
    }
    float m = s * (1.0f / 128.0f);
    float var = q * (1.0f / 128.0f) - m * m;
    float inv = rsqrtf(var + 1e-5f);
    return make_float4((v.x-m)*inv, (v.y-m)*inv, (v.z-m)*inv, (v.w-m)*inv);
}
__device__ __forceinline__ unsigned packbf(float lo, float hi) {
    __nv_bfloat162 h = __floats2bfloat162_rn(lo, hi);
    return *reinterpret_cast<unsigned*>(&h);
}
__device__ __forceinline__ float2 unpk(unsigned u) {
    __nv_bfloat162 h = *reinterpret_cast<__nv_bfloat162*>(&u);
    return __bfloat1622float2(h);
}
__device__ __forceinline__ float4 cvt4u(uint2 u) {
    float2 a = unpk(u.x), b = unpk(u.y);
    return make_float4(a.x, a.y, b.x, b.y);
}
__device__ __forceinline__ unsigned smaddr(const void* p) {
    unsigned a;
    asm("{ .reg .u64 t; cvta.to.shared.u64 t, %1; cvt.u32.u64 %0, t; }" : "=r"(a) : "l"(p));
    return a;
}
__device__ __forceinline__ void ldsm4(unsigned* r, unsigned addr) {
    asm volatile("ldmatrix.sync.aligned.m8n8.x4.shared.b16 {%0,%1,%2,%3}, [%4];"
        : "=r"(r[0]), "=r"(r[1]), "=r"(r[2]), "=r"(r[3]) : "r"(addr));
}
__device__ __forceinline__ void mma16(float* d, const unsigned* a, unsigned b0, unsigned b1) {
    asm volatile("mma.sync.aligned.m16n8k16.row.col.f32.bf16.bf16.f32 "
        "{%0,%1,%2,%3}, {%4,%5,%6,%7}, {%8,%9}, {%0,%1,%2,%3};"
        : "+f"(d[0]), "+f"(d[1]), "+f"(d[2]), "+f"(d[3])
        : "r"(a[0]), "r"(a[1]), "r"(a[2]), "r"(a[3]), "r"(b0), "r"(b1));
}
// warp tile M32 x N32, one k16 step; separate A/B smem row strides
template<int RSA, int RSB>
__device__ __forceinline__ void mma_g(float (&d)[2][4][4], unsigned aBase, unsigned bBase, int ks) {
    const unsigned kb = ks * 32;
    unsigned a0[4], a1[4];
    ldsm4(a0, aBase + kb);
    ldsm4(a1, aBase + 16*RSA*4 + kb);
    #pragma unroll
    for (int q = 0; q < 2; q++) {
        unsigned b[4];
        ldsm4(b, bBase + q*16*RSB*4 + kb);
        mma16(d[0][2*q],   a0, b[0], b[1]);
        mma16(d[1][2*q],   a1, b[0], b[1]);
        mma16(d[0][2*q+1], a0, b[2], b[3]);
        mma16(d[1][2*q+1], a1, b[2], b[3]);
    }
}

// warp spmm of one row, 8-deep MLP, pre-scaled byte offsets
__device__ __forceinline__ float4 spmm_row_sc(const int* __restrict__ rp, const unsigned* __restrict__ offs,
                                              const float* __restrict__ vals,
                                              const char* __restrict__ XbL /* Xb + lane*8 */, int r)
{
    float4 a0 = make_float4(0.f,0.f,0.f,0.f), a1 = a0, a2 = a0, a3 = a0;
    int s = rp[r], e = rp[r + 1], ed = s;
    for (; ed + 7 < e; ed += 8) {
        unsigned o[8]; float v[8]; uint2 u[8];
        #pragma unroll
        for (int j = 0; j < 8; j++) { o[j] = offs[ed+j]; v[j] = vals[ed+j]; }
        #pragma unroll
        for (int j = 0; j < 8; j++) u[j] = *(const uint2*)(XbL + o[j]);
        fma4(a0, cvt4u(u[0]), v[0]); fma4(a1, cvt4u(u[1]), v[1]);
        fma4(a2, cvt4u(u[2]), v[2]); fma4(a3, cvt4u(u[3]), v[3]);
        fma4(a0, cvt4u(u[4]), v[4]); fma4(a1, cvt4u(u[5]), v[5]);
        fma4(a2, cvt4u(u[6]), v[6]); fma4(a3, cvt4u(u[7]), v[7]);
    }
    for (; ed + 3 < e; ed += 4) {
        unsigned o[4]; float v[4]; uint2 u[4];
        #pragma unroll
        for (int j = 0; j < 4; j++) { o[j] = offs[ed+j]; v[j] = vals[ed+j]; }
        #pragma unroll
        for (int j = 0; j < 4; j++) u[j] = *(const uint2*)(XbL + o[j]);
        fma4(a0, cvt4u(u[0]), v[0]); fma4(a1, cvt4u(u[1]), v[1]);
        fma4(a2, cvt4u(u[2]), v[2]); fma4(a3, cvt4u(u[3]), v[3]);
    }
    for (; ed < e; ed++) {
        uint2 u = *(const uint2*)(XbL + offs[ed]);
        fma4(a0, cvt4u(u), vals[ed]);
    }
    a0.x += a1.x + a2.x + a3.x; a0.y += a1.y + a2.y + a3.y;
    a0.z += a1.z + a2.z + a3.z; a0.w += a1.w + a2.w + a3.w;
    return a0;
}

// ---------------- row_ptr + scaled offsets from sorted COO rows ----------------
__global__ void k_rowptr(const int* __restrict__ rows, const int* __restrict__ cols,
                         int E, int N, int* __restrict__ rp, unsigned* __restrict__ offs)
{
    for (int e = blockIdx.x * blockDim.x + threadIdx.x; e < E; e += gridDim.x * blockDim.x) {
        offs[e] = ((unsigned)cols[e]) << 8;   // *128 elems *2 bytes
        int r = rows[e];
        int prev = (e == 0) ? -1 : rows[e - 1];
        for (int rr = prev + 1; rr <= r; rr++) rp[rr] = e;
        if (e == E - 1) for (int rr = r + 1; rr <= N; rr++) rp[rr] = E;
    }
}

// ======================================================================
// k_nf: fused  t2 = inorm(inorm(X)@Wr^T+br);  out = sigmoid([EMB,t2]@Wf^T+bf)
// 512 threads, 1 block/SM. M128 tile, 16 warps (4x4 of M32xN32).
// ======================================================================
__global__ void __launch_bounds__(512, 1)
k_nf(const float* __restrict__ X1, const float* __restrict__ EMB1,
     const float* __restrict__ WF1, const float* __restrict__ BF1,
     __nv_bfloat16* __restrict__ out1, int N1,
     const float* __restrict__ X2, const float* __restrict__ EMB2,
     const float* __restrict__ WF2, const float* __restrict__ BF2,
     __nv_bfloat16* __restrict__ out2, int N2,
     const float* __restrict__ WR, const float* __restrict__ BR, int SPLIT)
{
    extern __shared__ __align__(16) unsigned smu[];
    unsigned* Asu = smu;                   // 128*RS2
    unsigned* W1u = Asu + 128 * RS2;       // 128*RS1 (red)
    unsigned* W2u = W1u + 128 * RS1;       // 128*RS2 (fus)
    float* bias1 = (float*)(W2u + 128 * RS2);
    float* bias2 = bias1 + 128;
    const int tid = threadIdx.x, lane = tid & 31, w = tid >> 5;
    const int qr = lane >> 2, qc = lane & 3;
    const int mbase = (w >> 2) * 32, nbase = (w & 3) * 32;

    const bool seg1 = (int)blockIdx.x < SPLIT;
    const int localBid = seg1 ? blockIdx.x : blockIdx.x - SPLIT;
    const int nb       = seg1 ? SPLIT : gridDim.x - SPLIT;
    const float* X   = seg1 ? X1 : X2;
    const float* EMB = seg1 ? EMB1 : EMB2;
    const float* WF  = seg1 ? WF1 : WF2;
    const float* BF  = seg1 ? BF1 : BF2;
    __nv_bfloat16* bout = seg1 ? out1 : out2;
    const int N = seg1 ? N1 : N2;

    for (int i = tid; i < 128 * 64; i += 512) {
        float2 wv = ((const float2*)WR)[i];
        W1u[(i >> 6) * RS1 + (i & 63)] = packbf(wv.x, wv.y);
    }
    for (int i = tid; i < 128 * 128; i += 512) {
        float2 wv = ((const float2*)WF)[i];
        W2u[(i >> 7) * RS2 + (i & 127)] = packbf(wv.x, wv.y);
    }
    if (tid < 128) bias1[tid] = BR[tid];
    else if (tid < 256) bias2[tid - 128] = BF[tid - 128];

    const unsigned smA = smaddr(Asu);
    const unsigned aBase2 = smA + (((mbase + (lane & 15)) * RS2 + ((lane >> 4) << 2)) << 2);
    const unsigned aBase1 = aBase2 + 64 * 4;  // t2 slot
    const unsigned b1Base = smaddr(W1u) + (((nbase + ((lane >> 4) << 3) + (lane & 7)) * RS1 + (((lane >> 3) & 1) << 2)) << 2);
    const unsigned b2Base = smaddr(W2u) + (((nbase + ((lane >> 4) << 3) + (lane & 7)) * RS2 + (((lane >> 3) & 1) << 2)) << 2);

    const int ntiles = (N + 127) >> 7;
    for (int tile = localBid; tile < ntiles; tile += nb) {
        __syncthreads();
        #pragma unroll 2
        for (int i = 0; i < 8; i++) {
            int rl = w * 8 + i, r = tile * 128 + rl;
            float4 xv = make_float4(0.f,0.f,0.f,0.f), ev = xv;
            if (r < N) {
                xv = *(const float4*)(X   + (size_t)r * 128 + lane * 4);
                ev = *(const float4*)(EMB + (size_t)r * 128 + lane * 4);
            }
            xv = inorm4(xv);
            unsigned* rowp = Asu + rl * RS2;
            uint2 se; se.x = packbf(ev.x, ev.y); se.y = packbf(ev.z, ev.w);
            uint2 sx; sx.x = packbf(xv.x, xv.y); sx.y = packbf(xv.z, xv.w);
            *(uint2*)(rowp + lane * 2)      = se;
            *(uint2*)(rowp + 64 + lane * 2) = sx;
        }
        __syncthreads();
        float d[2][4][4];
        #pragma unroll
        for (int t = 0; t < 2; t++)
            #pragma unroll
            for (int nt = 0; nt < 4; nt++)
                #pragma unroll
                for (int j = 0; j < 4; j++) d[t][nt][j] = 0.f;
        #pragma unroll
        for (int ks = 0; ks < 8; ks++) mma_g<RS2, RS1>(d, aBase1, b1Base, ks);
        __syncthreads();
        #pragma unroll
        for (int t = 0; t < 2; t++)
            #pragma unroll
            for (int nt = 0; nt < 4; nt++) {
                int col = nbase + nt * 8 + qc * 2;
                float b0 = bias1[col], b1 = bias1[col + 1];
                int row0 = mbase + t * 16 + qr;
                int wj = 64 + (col >> 1);
                Asu[row0 * RS2 + wj]       = packbf(d[t][nt][0] + b0, d[t][nt][1] + b1);
                Asu[(row0 + 8) * RS2 + wj] = packbf(d[t][nt][2] + b0, d[t][nt][3] + b1);
            }
        __syncthreads();
        #pragma unroll 2
        for (int i = 0; i < 8; i++) {
            int rl = w * 8 + i;
            uint2 u = *(const uint2*)(Asu + rl * RS2 + 64 + lane * 2);
            float4 o = inorm4(cvt4u(u));
            uint2 st; st.x = packbf(o.x, o.y); st.y = packbf(o.z, o.w);
            *(uint2*)(Asu + rl * RS2 + 64 + lane * 2) = st;
        }
        __syncthreads();
        #pragma unroll
        for (int t = 0; t < 2; t++)
            #pragma unroll
            for (int nt = 0; nt < 4; nt++)
                #pragma unroll
                for (int j = 0; j < 4; j++) d[t][nt][j] = 0.f;
        #pragma unroll
        for (int ks = 0; ks < 16; ks++) mma_g<RS2, RS2>(d, aBase2, b2Base, ks);
        #pragma unroll
        for (int t = 0; t < 2; t++)
            #pragma unroll
            for (int nt = 0; nt < 4; nt++) {
                int col = nbase + nt * 8 + qc * 2;
                float b0 = bias2[col], b1 = bias2[col + 1];
                #pragma unroll
                for (int h = 0; h < 2; h++) {
                    int r = tile * 128 + mbase + t * 16 + qr + h * 8;
                    if (r < N) {
                        float s0 = sigf(d[t][nt][2*h]   + b0);
                        float s1 = sigf(d[t][nt][2*h+1] + b1);
                        *(unsigned*)(bout + (size_t)r * 128 + col) = packbf(s0, s1);
                    }
                }
            }
    }
}

// ==== social layer (+ optional fused combine) + optional tail spmm, 4 blocks/SM ====
__global__ void __launch_bounds__(256, 4)
k_social(const int* __restrict__ rp, const unsigned* __restrict__ offs, const float* __restrict__ vals,
         const __nv_bfloat16* __restrict__ Xb, const float* __restrict__ W, const float* __restrict__ Bv,
         __nv_bfloat16* __restrict__ bout,
         const __nv_bfloat16* __restrict__ addA, const __nv_bfloat16* __restrict__ addB, int N,
         const int* __restrict__ t_rp, const unsigned* __restrict__ t_offs, const float* __restrict__ t_vals,
         const __nv_bfloat16* __restrict__ t_X, __nv_bfloat16* __restrict__ t_out, int t_N)
{
    extern __shared__ __align__(16) unsigned smu[];
    unsigned* Asu = smu;                 // 64*RS1
    unsigned* Wsu = Asu + 64 * RS1;      // 128*RS1
    float*    biasf = (float*)(Wsu + 128 * RS1);
    const int tid = threadIdx.x, lane = tid & 31, w = tid >> 5;
    const int qr = lane >> 2, qc = lane & 3;
    const int mbase = (w >> 2) * 32, nbase = (w & 3) * 32;

    for (int i = tid; i < 128 * 64; i += 256) {
        float2 wv = ((const float2*)W)[i];
        Wsu[(i >> 6) * RS1 + (i & 63)] = packbf(wv.x, wv.y);
    }
    if (tid < 128) biasf[tid] = Bv[tid];

    const unsigned aBase = smaddr(Asu) + (((mbase + (lane & 15)) * RS1 + ((lane >> 4) << 2)) << 2);
    const unsigned bBase = smaddr(Wsu) + (((nbase + ((lane >> 4) << 3) + (lane & 7)) * RS1 + (((lane >> 3) & 1) << 2)) << 2);
    const char* XbL = (const char*)Xb + lane * 8;

    int ntiles = (N + 63) >> 6;
    for (int tile = blockIdx.x; tile < ntiles; tile += gridDim.x) {
        __syncthreads();
        for (int i = 0; i < 8; i++) {
            int rl = w * 8 + i, r = tile * 64 + rl;
            float4 a0 = make_float4(0.f,0.f,0.f,0.f);
            if (r < N) a0 = spmm_row_sc(rp, offs, vals, XbL, r);
            uint2 st; st.x = packbf(a0.x, a0.y); st.y = packbf(a0.z, a0.w);
            *(uint2*)(Asu + rl * RS1 + lane * 2) = st;
        }
        __syncthreads();
        float d[2][4][4];
        #pragma unroll
        for (int t = 0; t < 2; t++)
            #pragma unroll
            for (int nt = 0; nt < 4; nt++)
                #pragma unroll
                for (int j = 0; j < 4; j++) d[t][nt][j] = 0.f;
        #pragma unroll
        for (int ks = 0; ks < 8; ks++) mma_g<RS1, RS1>(d, aBase, bBase, ks);
        #pragma unroll
        for (int t = 0; t < 2; t++)
            #pragma unroll
            for (int nt = 0; nt < 4; nt++) {
                int col = nbase + nt * 8 + qc * 2;
                float b0 = biasf[col], b1 = biasf[col + 1];
                #pragma unroll
                for (int h = 0; h < 2; h++) {
                    int r = tile * 64 + mbase + t * 16 + qr + h * 8;
                    if (r < N) {
                        float s0 = sigf(fmaxf(d[t][nt][2*h]   + b0, 0.f));
                        float s1 = sigf(fmaxf(d[t][nt][2*h+1] + b1, 0.f));
                        if (addA) {
                            float2 pa = unpk(*(const unsigned*)(addA + (size_t)r * 128 + col));
                            float2 pb = unpk(*(const unsigned*)(addB + (size_t)r * 128 + col));
                            s0 = sigf((s0 + pa.x + pb.x) * 0.5f);
                            s1 = sigf((s1 + pa.y + pb.y) * 0.5f);
                        }
                        *(unsigned*)(bout + (size_t)r * 128 + col) = packbf(s0, s1);
                    }
                }
            }
    }
    // tail: independent spmm (g_from_items), sigmoid epilogue, bf16 out
    if (t_out) {
        const char* tXL = (const char*)t_X + lane * 8;
        for (int r = blockIdx.x * 8 + w; r < t_N; r += gridDim.x * 8) {
            float4 o0 = spmm_row_sc(t_rp, t_offs, t_vals, tXL, r);
            uint2 st; st.x = packbf(sigf(o0.x), sigf(o0.y)); st.y = packbf(sigf(o0.z), sigf(o0.w));
            *(uint2*)(t_out + (size_t)r * 128 + lane * 4) = st;
        }
    }
}

// ---------------- scoring with fused all_neighbors spmm (bf16 inputs) ----------------
__global__ void __launch_bounds__(256)
k_score(const int* __restrict__ gid, const int* __restrict__ iid,
        const __nv_bfloat16* __restrict__ FG, const __nv_bfloat16* __restrict__ FI,
        const int* __restrict__ rp, const unsigned* __restrict__ offs, const float* __restrict__ vals,
        float* __restrict__ out, int B)
{
    int widx = (blockIdx.x * blockDim.x + threadIdx.x) >> 5;
    int lane = threadIdx.x & 31;
    if (widx >= B) return;
    int g = gid[widx], it = iid[widx];
    float4 ge = cvt4u(((const uint2*)(FG + (size_t)g  * 128))[lane]);
    float4 ie = cvt4u(((const uint2*)(FI + (size_t)it * 128))[lane]);
    const char* FGL = (const char*)FG + lane * 8;
    float4 ne = spmm_row_sc(rp, offs, vals, FGL, g);
    float d1 = ge.x*ie.x + ge.y*ie.y + ge.z*ie.z + ge.w*ie.w;
    float d2 = ne.x*(ge.x+ie.x) + ne.y*(ge.y+ie.y) + ne.z*(ge.z+ie.z) + ne.w*(ge.w+ie.w);
    d1 = wredsum(d1); d2 = wredsum(d2);
    if (lane == 0) { out[widx] = d1; out[B + widx] = d2; }
}

// ---------------- launch ----------------
extern "C" void kernel_launch(void* const* d_in, const int* in_sizes, int n_in,
                              void* d_out, int out_size)
{
    const int*   group_ids   = (const int*)d_in[0];
    const int*   item_ids    = (const int*)d_in[1];
    const int*   gi_rows     = (const int*)d_in[2];
    const int*   gi_cols     = (const int*)d_in[3];
    const float* gi_vals     = (const float*)d_in[4];
    const int*   gg_rows     = (const int*)d_in[5];
    const int*   gg_cols     = (const int*)d_in[6];
    const float* gg_vals     = (const float*)d_in[7];
    const float* g_feat      = (const float*)d_in[8];
    const float* i_feat      = (const float*)d_in[9];
    const float* emb_group   = (const float*)d_in[10];
    const float* emb_item    = (const float*)d_in[11];
    const float* W_w         = (const float*)d_in[12];
    const float* W_b         = (const float*)d_in[13];
    const float* red_w       = (const float*)d_in[14];
    const float* red_b       = (const float*)d_in[15];
    const float* item_fus_w  = (const float*)d_in[16];
    const float* item_fus_b  = (const float*)d_in[17];
    const float* group_fus_w = (const float*)d_in[18];
    const float* group_fus_b = (const float*)d_in[19];
    float* out = (float*)d_out;

    int B   = in_sizes[0];
    int Egi = in_sizes[2];  if (Egi > E_CAP) Egi = E_CAP;
    int Egg = in_sizes[5];  if (Egg > E_CAP) Egg = E_CAP;
    int NG  = in_sizes[8] / 128;  if (NG > NG_CAP) NG = NG_CAP;
    int NI  = in_sizes[9] / 128;  if (NI > NI_CAP) NI = NI_CAP;

    __nv_bfloat16 *pb_fi, *pb_fg, *pb_gfi, *pb_first, *pb_fgrp;
    int *p_rp_gi, *p_rp_gg;
    unsigned *p_off_gi, *p_off_gg;
    cudaGetSymbolAddress((void**)&pb_fi,    b_fi);
    cudaGetSymbolAddress((void**)&pb_fg,    b_fg);
    cudaGetSymbolAddress((void**)&pb_gfi,   b_gfi);
    cudaGetSymbolAddress((void**)&pb_first, b_first);
    cudaGetSymbolAddress((void**)&pb_fgrp,  b_fgrp);
    cudaGetSymbolAddress((void**)&p_rp_gi,  g_rp_gi);
    cudaGetSymbolAddress((void**)&p_rp_gg,  g_rp_gg);
    cudaGetSymbolAddress((void**)&p_off_gi, g_off_gi);
    cudaGetSymbolAddress((void**)&p_off_gg, g_off_gg);

    size_t smemS  = (size_t)(64 * RS1 + 128 * RS1) * 4 + 512;                 // ~52.7 KB (4/SM)
    size_t smemNF = (size_t)(128 * RS2 + 128 * RS1 + 128 * RS2) * 4 + 1024;   // ~167 KB (1/SM)
    cudaFuncSetAttribute(k_nf,     cudaFuncAttributeMaxDynamicSharedMemorySize, (int)smemNF);
    cudaFuncSetAttribute(k_social, cudaFuncAttributeMaxDynamicSharedMemorySize, (int)smemS);

    const int PGRID4 = 592;   // 4 blocks/SM
    int tI = (NI + 127) >> 7, tG = (NG + 127) >> 7;
    int SPLIT = (int)((long long)148 * tI / (tI + tG));
    if (SPLIT < 1) SPLIT = 1;
    if (SPLIT > 147) SPLIT = 147;

    k_rowptr<<<1024, 256>>>(gi_rows, gi_cols, Egi, NG, p_rp_gi, p_off_gi);
    k_rowptr<<<1024, 256>>>(gg_rows, gg_cols, Egg, NG, p_rp_gg, p_off_gg);

    // fused nln+fus: final_item and fus_group directly from raw inputs
    k_nf<<<148, 512, smemNF>>>(i_feat, emb_item,  item_fus_w,  item_fus_b,  pb_fi, NI,
                               g_feat, emb_group, group_fus_w, group_fus_b, pb_fg, NG,
                               red_w, red_b, SPLIT);

    // social layer 1 + tail spmm_gi (g_from_items)
    k_social<<<PGRID4, 256, smemS>>>(p_rp_gg, p_off_gg, gg_vals, pb_fg, W_w, W_b,
                                     pb_first, nullptr, nullptr, NG,
                                     p_rp_gi, p_off_gi, gi_vals, pb_fi, pb_gfi, NG);

    // social layer 2 fused with final_group combine
    k_social<<<PGRID4, 256, smemS>>>(p_rp_gg, p_off_gg, gg_vals, pb_first, W_w, W_b,
                                     pb_fgrp, pb_gfi, pb_first, NG,
                                     nullptr, nullptr, nullptr, nullptr, nullptr, 0);

    // scoring with fused all_neighbors spmm
    k_score<<<(B + 7) / 8, 256>>>(group_ids, item_ids, pb_fgrp, pb_fi,
                                  p_rp_gg, p_off_gg, gg_vals, out, B);
}

// round 15
// speedup vs baseline: 1.0352x; 1.0352x over previous
#include <cuda_runtime.h>
#include <cuda_bf16.h>
#include <cstdio>

#define FULLMASK 0xffffffffu
#define NG_CAP 50000
#define NI_CAP 100000
#define RS1 68     // smem row stride (u32 words) K=128 tiles
#define RS2 132    // smem row stride (u32 words) K=256 tiles

// ---------------- scratch (device globals) ----------------
__device__ __nv_bfloat16 b_fi   [NI_CAP * 128]; // final_item
__device__ __nv_bfloat16 b_fg   [NG_CAP * 128]; // fus_group
__device__ __nv_bfloat16 b_gfi  [NG_CAP * 128]; // sigmoid(spmm(gi, fi))
__device__ __nv_bfloat16 b_first[NG_CAP * 128]; // first
__device__ __nv_bfloat16 b_fgrp [NG_CAP * 128]; // final_group
__device__ int g_rp_gi[NG_CAP + 1];
__device__ int g_rp_gg[NG_CAP + 1];

// ---------------- helpers ----------------
__device__ __forceinline__ float wredsum(float v) {
    #pragma unroll
    for (int o = 16; o; o >>= 1) v += __shfl_xor_sync(FULLMASK, v, o);
    return v;
}
__device__ __forceinline__ float sigf(float x) { return 1.0f / (1.0f + __expf(-x)); }
__device__ __forceinline__ float4 inorm4(float4 v) {
    float s = v.x + v.y + v.z + v.w;
    float q = v.x*v.x + v.y*v.y + v.z*v.z + v.w*v.w;
    #pragma unroll
    for (int o = 16; o; o >>= 1) {
        s += __shfl_xor_sync(FULLMASK, s, o);
        q += __shfl_xor_sync(FULLMASK, q, o);
    }
    float m = s * (1.0f / 128.0f);
    float var = q * (1.0f / 128.0f) - m * m;
    float inv = rsqrtf(var + 1e-5f);
    return make_float4((v.x-m)*inv, (v.y-m)*inv, (v.z-m)*inv, (v.w-m)*inv);
}
__device__ __forceinline__ unsigned packbf(float lo, float hi) {
    __nv_bfloat162 h = __floats2bfloat162_rn(lo, hi);
    return *reinterpret_cast<unsigned*>(&h);
}
__device__ __forceinline__ float2 unpk(unsigned u) {
    __nv_bfloat162 h = *reinterpret_cast<__nv_bfloat162*>(&u);
    return __bfloat1622float2(h);
}
__device__ __forceinline__ float4 cvt4u(uint2 u) {
    float2 a = unpk(u.x), b = unpk(u.y);
    return make_float4(a.x, a.y, b.x, b.y);
}
// ---- f32x2 packed FMA path (bit-identical f32 rounding, half the FMA issues) ----
__device__ __forceinline__ unsigned long long bf2f2(unsigned u) {
    unsigned lo = u << 16, hi = u & 0xffff0000u;
    unsigned long long r;
    asm("mov.b64 %0, {%1,%2};" : "=l"(r) : "r"(lo), "r"(hi));
    return r;
}
__device__ __forceinline__ unsigned long long packf2(float v) {
    unsigned long long r;
    asm("mov.b64 %0, {%1,%2};" : "=l"(r) : "f"(v), "f"(v));
    return r;
}
__device__ __forceinline__ void fma2(unsigned long long& d, unsigned long long a, unsigned long long b) {
    asm("fma.rn.f32x2 %0, %1, %2, %0;" : "+l"(d) : "l"(a), "l"(b));
}
__device__ __forceinline__ float2 unpf2(unsigned long long r) {
    float x, y;
    asm("mov.b64 {%0,%1}, %2;" : "=f"(x), "=f"(y) : "l"(r));
    return make_float2(x, y);
}
__device__ __forceinline__ unsigned smaddr(const void* p) {
    unsigned a;
    asm("{ .reg .u64 t; cvta.to.shared.u64 t, %1; cvt.u32.u64 %0, t; }" : "=r"(a) : "l"(p));
    return a;
}
__device__ __forceinline__ void ldsm4(unsigned* r, unsigned addr) {
    asm volatile("ldmatrix.sync.aligned.m8n8.x4.shared.b16 {%0,%1,%2,%3}, [%4];"
        : "=r"(r[0]), "=r"(r[1]), "=r"(r[2]), "=r"(r[3]) : "r"(addr));
}
__device__ __forceinline__ void mma16(float* d, const unsigned* a, unsigned b0, unsigned b1) {
    asm volatile("mma.sync.aligned.m16n8k16.row.col.f32.bf16.bf16.f32 "
        "{%0,%1,%2,%3}, {%4,%5,%6,%7}, {%8,%9}, {%0,%1,%2,%3};"
        : "+f"(d[0]), "+f"(d[1]), "+f"(d[2]), "+f"(d[3])
        : "r"(a[0]), "r"(a[1]), "r"(a[2]), "r"(a[3]), "r"(b0), "r"(b1));
}
template<int RSA, int RSB>
__device__ __forceinline__ void mma_g(float (&d)[2][4][4], unsigned aBase, unsigned bBase, int ks) {
    const unsigned kb = ks * 32;
    unsigned a0[4], a1[4];
    ldsm4(a0, aBase + kb);
    ldsm4(a1, aBase + 16*RSA*4 + kb);
    #pragma unroll
    for (int q = 0; q < 2; q++) {
        unsigned b[4];
        ldsm4(b, bBase + q*16*RSB*4 + kb);
        mma16(d[0][2*q],   a0, b[0], b[1]);
        mma16(d[1][2*q],   a1, b[0], b[1]);
        mma16(d[0][2*q+1], a0, b[2], b[3]);
        mma16(d[1][2*q+1], a1, b[2], b[3]);
    }
}

// warp spmm of one row, 8-deep MLP, f32x2 accumulation (k_score)
__device__ __forceinline__ float4 spmm_row(const int* __restrict__ rp, const int* __restrict__ cols,
                                           const float* __restrict__ vals,
                                           const __nv_bfloat16* __restrict__ Xb, int r, int lane)
{
    unsigned long long aA0=0,aA1=0,aB0=0,aB1=0,aC0=0,aC1=0,aD0=0,aD1=0;
    int s = rp[r], e = rp[r + 1], ed = s;
    for (; ed + 7 < e; ed += 8) {
        int c[8]; float v[8]; uint2 u[8];
        #pragma unroll
        for (int j = 0; j < 8; j++) { c[j] = cols[ed+j]; v[j] = vals[ed+j]; }
        #pragma unroll
        for (int j = 0; j < 8; j++) u[j] = ((const uint2*)(Xb + (size_t)c[j] * 128))[lane];
        { unsigned long long w = packf2(v[0]); fma2(aA0, bf2f2(u[0].x), w); fma2(aA1, bf2f2(u[0].y), w); }
        { unsigned long long w = packf2(v[1]); fma2(aB0, bf2f2(u[1].x), w); fma2(aB1, bf2f2(u[1].y), w); }
        { unsigned long long w = packf2(v[2]); fma2(aC0, bf2f2(u[2].x), w); fma2(aC1, bf2f2(u[2].y), w); }
        { unsigned long long w = packf2(v[3]); fma2(aD0, bf2f2(u[3].x), w); fma2(aD1, bf2f2(u[3].y), w); }
        { unsigned long long w = packf2(v[4]); fma2(aA0, bf2f2(u[4].x), w); fma2(aA1, bf2f2(u[4].y), w); }
        { unsigned long long w = packf2(v[5]); fma2(aB0, bf2f2(u[5].x), w); fma2(aB1, bf2f2(u[5].y), w); }
        { unsigned long long w = packf2(v[6]); fma2(aC0, bf2f2(u[6].x), w); fma2(aC1, bf2f2(u[6].y), w); }
        { unsigned long long w = packf2(v[7]); fma2(aD0, bf2f2(u[7].x), w); fma2(aD1, bf2f2(u[7].y), w); }
    }
    for (; ed + 3 < e; ed += 4) {
        int c[4]; float v[4]; uint2 u[4];
        #pragma unroll
        for (int j = 0; j < 4; j++) { c[j] = cols[ed+j]; v[j] = vals[ed+j]; }
        #pragma unroll
        for (int j = 0; j < 4; j++) u[j] = ((const uint2*)(Xb + (size_t)c[j] * 128))[lane];
        { unsigned long long w = packf2(v[0]); fma2(aA0, bf2f2(u[0].x), w); fma2(aA1, bf2f2(u[0].y), w); }
        { unsigned long long w = packf2(v[1]); fma2(aB0, bf2f2(u[1].x), w); fma2(aB1, bf2f2(u[1].y), w); }
        { unsigned long long w = packf2(v[2]); fma2(aC0, bf2f2(u[2].x), w); fma2(aC1, bf2f2(u[2].y), w); }
        { unsigned long long w = packf2(v[3]); fma2(aD0, bf2f2(u[3].x), w); fma2(aD1, bf2f2(u[3].y), w); }
    }
    for (; ed < e; ed++) {
        uint2 u = ((const uint2*)(Xb + (size_t)cols[ed] * 128))[lane];
        unsigned long long w = packf2(vals[ed]);
        fma2(aA0, bf2f2(u.x), w); fma2(aA1, bf2f2(u.y), w);
    }
    float2 pa = unpf2(aA0), pb = unpf2(aB0), pc = unpf2(aC0), pd = unpf2(aD0);
    float2 qa = unpf2(aA1), qb = unpf2(aB1), qc2 = unpf2(aC1), qd = unpf2(aD1);
    return make_float4(pa.x + pb.x + pc.x + pd.x, pa.y + pb.y + pc.y + pd.y,
                       qa.x + qb.x + qc2.x + qd.x, qa.y + qb.y + qc2.y + qd.y);
}

// paired-row spmm, f32x2 accumulation (socials + gi tail)
__device__ __forceinline__ void spmm_pair(const int* __restrict__ rp, const int* __restrict__ cols,
                                          const float* __restrict__ vals,
                                          const __nv_bfloat16* __restrict__ Xb,
                                          int r0, int r1, int N, int lane,
                                          float4& out0, float4& out1)
{
    unsigned long long pA0=0,pA1=0,pB0=0,pB1=0;  // row0 streams A,B x (elems01, elems23)
    unsigned long long qA0=0,qA1=0,qB0=0,qB1=0;  // row1
    int e0 = 0, e1 = 0, ed0 = 0, ed1 = 0;
    if (r0 < N) { ed0 = rp[r0]; e0 = rp[r0 + 1]; }
    if (r1 < N) { ed1 = rp[r1]; e1 = rp[r1 + 1]; }
    while (ed0 + 3 < e0 && ed1 + 3 < e1) {
        int c0[4], c1[4]; float v0[4], v1[4]; uint2 u0[4], u1[4];
        #pragma unroll
        for (int j = 0; j < 4; j++) { c0[j] = cols[ed0+j]; v0[j] = vals[ed0+j]; }
        #pragma unroll
        for (int j = 0; j < 4; j++) { c1[j] = cols[ed1+j]; v1[j] = vals[ed1+j]; }
        #pragma unroll
        for (int j = 0; j < 4; j++) u0[j] = ((const uint2*)(Xb + (size_t)c0[j] * 128))[lane];
        #pragma unroll
        for (int j = 0; j < 4; j++) u1[j] = ((const uint2*)(Xb + (size_t)c1[j] * 128))[lane];
        { unsigned long long w = packf2(v0[0]); fma2(pA0, bf2f2(u0[0].x), w); fma2(pA1, bf2f2(u0[0].y), w); }
        { unsigned long long w = packf2(v0[1]); fma2(pB0, bf2f2(u0[1].x), w); fma2(pB1, bf2f2(u0[1].y), w); }
        { unsigned long long w = packf2(v0[2]); fma2(pA0, bf2f2(u0[2].x), w); fma2(pA1, bf2f2(u0[2].y), w); }
        { unsigned long long w = packf2(v0[3]); fma2(pB0, bf2f2(u0[3].x), w); fma2(pB1, bf2f2(u0[3].y), w); }
        { unsigned long long w = packf2(v1[0]); fma2(qA0, bf2f2(u1[0].x), w); fma2(qA1, bf2f2(u1[0].y), w); }
        { unsigned long long w = packf2(v1[1]); fma2(qB0, bf2f2(u1[1].x), w); fma2(qB1, bf2f2(u1[1].y), w); }
        { unsigned long long w = packf2(v1[2]); fma2(qA0, bf2f2(u1[2].x), w); fma2(qA1, bf2f2(u1[2].y), w); }
        { unsigned long long w = packf2(v1[3]); fma2(qB0, bf2f2(u1[3].x), w); fma2(qB1, bf2f2(u1[3].y), w); }
        ed0 += 4; ed1 += 4;
    }
    for (; ed0 + 3 < e0; ed0 += 4) {
        int c[4]; float v[4]; uint2 u[4];
        #pragma unroll
        for (int j = 0; j < 4; j++) { c[j] = cols[ed0+j]; v[j] = vals[ed0+j]; }
        #pragma unroll
        for (int j = 0; j < 4; j++) u[j] = ((const uint2*)(Xb + (size_t)c[j] * 128))[lane];
        { unsigned long long w = packf2(v[0]); fma2(pA0, bf2f2(u[0].x), w); fma2(pA1, bf2f2(u[0].y), w); }
        { unsigned long long w = packf2(v[1]); fma2(pB0, bf2f2(u[1].x), w); fma2(pB1, bf2f2(u[1].y), w); }
        { unsigned long long w = packf2(v[2]); fma2(pA0, bf2f2(u[2].x), w); fma2(pA1, bf2f2(u[2].y), w); }
        { unsigned long long w = packf2(v[3]); fma2(pB0, bf2f2(u[3].x), w); fma2(pB1, bf2f2(u[3].y), w); }
    }
    for (; ed0 < e0; ed0++) {
        uint2 u = ((const uint2*)(Xb + (size_t)cols[ed0] * 128))[lane];
        unsigned long long w = packf2(vals[ed0]);
        fma2(pA0, bf2f2(u.x), w); fma2(pA1, bf2f2(u.y), w);
    }
    for (; ed1 + 3 < e1; ed1 += 4) {
        int c[4]; float v[4]; uint2 u[4];
        #pragma unroll
        for (int j = 0; j < 4; j++) { c[j] = cols[ed1+j]; v[j] = vals[ed1+j]; }
        #pragma unroll
        for (int j = 0; j < 4; j++) u[j] = ((const uint2*)(Xb + (size_t)c[j] * 128))[lane];
        { unsigned long long w = packf2(v[0]); fma2(qA0, bf2f2(u[0].x), w); fma2(qA1, bf2f2(u[0].y), w); }
        { unsigned long long w = packf2(v[1]); fma2(qB0, bf2f2(u[1].x), w); fma2(qB1, bf2f2(u[1].y), w); }
        { unsigned long long w = packf2(v[2]); fma2(qA0, bf2f2(u[2].x), w); fma2(qA1, bf2f2(u[2].y), w); }
        { unsigned long long w = packf2(v[3]); fma2(qB0, bf2f2(u[3].x), w); fma2(qB1, bf2f2(u[3].y), w); }
    }
    for (; ed1 < e1; ed1++) {
        uint2 u = ((const uint2*)(Xb + (size_t)cols[ed1] * 128))[lane];
        unsigned long long w = packf2(vals[ed1]);
        fma2(qA0, bf2f2(u.x), w); fma2(qA1, bf2f2(u.y), w);
    }
    {
        float2 a = unpf2(pA0), b = unpf2(pB0), cc = unpf2(pA1), dd = unpf2(pB1);
        out0 = make_float4(a.x + b.x, a.y + b.y, cc.x + dd.x, cc.y + dd.y);
    }
    {
        float2 a = unpf2(qA0), b = unpf2(qB0), cc = unpf2(qA1), dd = unpf2(qB1);
        out1 = make_float4(a.x + b.x, a.y + b.y, cc.x + dd.x, cc.y + dd.y);
    }
}

// ---------------- merged row_ptr builder (both edge lists in one launch) ----------------
__global__ void k_rowptr2(const int* __restrict__ rowsA, int EA, int NA, int* __restrict__ rpA,
                          const int* __restrict__ rowsB, int EB, int NB, int* __restrict__ rpB)
{
    int total = EA + EB;
    for (int idx = blockIdx.x * blockDim.x + threadIdx.x; idx < total; idx += gridDim.x * blockDim.x) {
        const int* rows; int e, E, N; int* rp;
        if (idx < EA) { rows = rowsA; e = idx; E = EA; N = NA; rp = rpA; }
        else          { rows = rowsB; e = idx - EA; E = EB; N = NB; rp = rpB; }
        int r = rows[e];
        int prev = (e == 0) ? -1 : rows[e - 1];
        for (int rr = prev + 1; rr <= r; rr++) rp[rr] = e;
        if (e == E - 1) for (int rr = r + 1; rr <= N; rr++) rp[rr] = E;
    }
}

// ======================================================================
// k_nf: fused  t2 = inorm(inorm(X)@Wr^T+br);  out = sigmoid([EMB,t2]@Wf^T+bf)
// 512 threads, 1 block/SM. M128 tile, 16 warps (4x4 of M32xN32).
// ======================================================================
__global__ void __launch_bounds__(512, 1)
k_nf(const float* __restrict__ X1, const float* __restrict__ EMB1,
     const float* __restrict__ WF1, const float* __restrict__ BF1,
     __nv_bfloat16* __restrict__ out1, int N1,
     const float* __restrict__ X2, const float* __restrict__ EMB2,
     const float* __restrict__ WF2, const float* __restrict__ BF2,
     __nv_bfloat16* __restrict__ out2, int N2,
     const float* __restrict__ WR, const float* __restrict__ BR, int SPLIT)
{
    extern __shared__ __align__(16) unsigned smu[];
    unsigned* Asu = smu;                   // 128*RS2
    unsigned* W1u = Asu + 128 * RS2;       // 128*RS1 (red)
    unsigned* W2u = W1u + 128 * RS1;       // 128*RS2 (fus)
    float* bias1 = (float*)(W2u + 128 * RS2);
    float* bias2 = bias1 + 128;
    const int tid = threadIdx.x, lane = tid & 31, w = tid >> 5;
    const int qr = lane >> 2, qc = lane & 3;
    const int mbase = (w >> 2) * 32, nbase = (w & 3) * 32;

    const bool seg1 = (int)blockIdx.x < SPLIT;
    const int localBid = seg1 ? blockIdx.x : blockIdx.x - SPLIT;
    const int nb       = seg1 ? SPLIT : gridDim.x - SPLIT;
    const float* X   = seg1 ? X1 : X2;
    const float* EMB = seg1 ? EMB1 : EMB2;
    const float* WF  = seg1 ? WF1 : WF2;
    const float* BF  = seg1 ? BF1 : BF2;
    __nv_bfloat16* bout = seg1 ? out1 : out2;
    const int N = seg1 ? N1 : N2;

    for (int i = tid; i < 128 * 64; i += 512) {
        float2 wv = ((const float2*)WR)[i];
        W1u[(i >> 6) * RS1 + (i & 63)] = packbf(wv.x, wv.y);
    }
    for (int i = tid; i < 128 * 128; i += 512) {
        float2 wv = ((const float2*)WF)[i];
        W2u[(i >> 7) * RS2 + (i & 127)] = packbf(wv.x, wv.y);
    }
    if (tid < 128) bias1[tid] = BR[tid];
    else if (tid < 256) bias2[tid - 128] = BF[tid - 128];

    const unsigned smA = smaddr(Asu);
    const unsigned aBase2 = smA + (((mbase + (lane & 15)) * RS2 + ((lane >> 4) << 2)) << 2);
    const unsigned aBase1 = aBase2 + 64 * 4;  // t2 slot
    const unsigned b1Base = smaddr(W1u) + (((nbase + ((lane >> 4) << 3) + (lane & 7)) * RS1 + (((lane >> 3) & 1) << 2)) << 2);
    const unsigned b2Base = smaddr(W2u) + (((nbase + ((lane >> 4) << 3) + (lane & 7)) * RS2 + (((lane >> 3) & 1) << 2)) << 2);

    const int ntiles = (N + 127) >> 7;
    for (int tile = localBid; tile < ntiles; tile += nb) {
        __syncthreads();
        #pragma unroll 2
        for (int i = 0; i < 8; i++) {
            int rl = w * 8 + i, r = tile * 128 + rl;
            float4 xv = make_float4(0.f,0.f,0.f,0.f), ev = xv;
            if (r < N) {
                xv = *(const float4*)(X   + (size_t)r * 128 + lane * 4);
                ev = *(const float4*)(EMB + (size_t)r * 128 + lane * 4);
            }
            xv = inorm4(xv);
            unsigned* rowp = Asu + rl * RS2;
            uint2 se; se.x = packbf(ev.x, ev.y); se.y = packbf(ev.z, ev.w);
            uint2 sx; sx.x = packbf(xv.x, xv.y); sx.y = packbf(xv.z, xv.w);
            *(uint2*)(rowp + lane * 2)      = se;
            *(uint2*)(rowp + 64 + lane * 2) = sx;
        }
        __syncthreads();
        float d[2][4][4];
        #pragma unroll
        for (int t = 0; t < 2; t++)
            #pragma unroll
            for (int nt = 0; nt < 4; nt++)
                #pragma unroll
                for (int j = 0; j < 4; j++) d[t][nt][j] = 0.f;
        #pragma unroll
        for (int ks = 0; ks < 8; ks++) mma_g<RS2, RS1>(d, aBase1, b1Base, ks);
        __syncthreads();
        #pragma unroll
        for (int t = 0; t < 2; t++)
            #pragma unroll
            for (int nt = 0; nt < 4; nt++) {
                int col = nbase + nt * 8 + qc * 2;
                float b0 = bias1[col], b1 = bias1[col + 1];
                int row0 = mbase + t * 16 + qr;
                int wj = 64 + (col >> 1);
                Asu[row0 * RS2 + wj]       = packbf(d[t][nt][0] + b0, d[t][nt][1] + b1);
                Asu[(row0 + 8) * RS2 + wj] = packbf(d[t][nt][2] + b0, d[t][nt][3] + b1);
            }
        __syncthreads();
        #pragma unroll 2
        for (int i = 0; i < 8; i++) {
            int rl = w * 8 + i;
            uint2 u = *(const uint2*)(Asu + rl * RS2 + 64 + lane * 2);
            float4 o = inorm4(cvt4u(u));
            uint2 st; st.x = packbf(o.x, o.y); st.y = packbf(o.z, o.w);
            *(uint2*)(Asu + rl * RS2 + 64 + lane * 2) = st;
        }
        __syncthreads();
        #pragma unroll
        for (int t = 0; t < 2; t++)
            #pragma unroll
            for (int nt = 0; nt < 4; nt++)
                #pragma unroll
                for (int j = 0; j < 4; j++) d[t][nt][j] = 0.f;
        #pragma unroll
        for (int ks = 0; ks < 16; ks++) mma_g<RS2, RS2>(d, aBase2, b2Base, ks);
        #pragma unroll
        for (int t = 0; t < 2; t++)
            #pragma unroll
            for (int nt = 0; nt < 4; nt++) {
                int col = nbase + nt * 8 + qc * 2;
                float b0 = bias2[col], b1 = bias2[col + 1];
                #pragma unroll
                for (int h = 0; h < 2; h++) {
                    int r = tile * 128 + mbase + t * 16 + qr + h * 8;
                    if (r < N) {
                        float s0 = sigf(d[t][nt][2*h]   + b0);
                        float s1 = sigf(d[t][nt][2*h+1] + b1);
                        *(unsigned*)(bout + (size_t)r * 128 + col) = packbf(s0, s1);
                    }
                }
            }
    }
}

// ==== social layer (+ optional fused combine, all bf16) + optional tail spmm, 3/SM ====
__global__ void __launch_bounds__(256, 3)
k_social(const int* __restrict__ rp, const int* __restrict__ cols, const float* __restrict__ vals,
         const __nv_bfloat16* __restrict__ Xb, const float* __restrict__ W, const float* __restrict__ Bv,
         __nv_bfloat16* __restrict__ bout,
         const __nv_bfloat16* __restrict__ addA, const __nv_bfloat16* __restrict__ addB, int N,
         const int* __restrict__ t_rp, const int* __restrict__ t_cols, const float* __restrict__ t_vals,
         const __nv_bfloat16* __restrict__ t_X, __nv_bfloat16* __restrict__ t_out, int t_N)
{
    extern __shared__ __align__(16) unsigned smu[];
    unsigned* Asu = smu;                 // 64*RS1
    unsigned* Wsu = Asu + 64 * RS1;      // 128*RS1
    float*    biasf = (float*)(Wsu + 128 * RS1);
    const int tid = threadIdx.x, lane = tid & 31, w = tid >> 5;
    const int qr = lane >> 2, qc = lane & 3;
    const int mbase = (w >> 2) * 32, nbase = (w & 3) * 32;

    for (int i = tid; i < 128 * 64; i += 256) {
        float2 wv = ((const float2*)W)[i];
        Wsu[(i >> 6) * RS1 + (i & 63)] = packbf(wv.x, wv.y);
    }
    if (tid < 128) biasf[tid] = Bv[tid];

    const unsigned aBase = smaddr(Asu) + (((mbase + (lane & 15)) * RS1 + ((lane >> 4) << 2)) << 2);
    const unsigned bBase = smaddr(Wsu) + (((nbase + ((lane >> 4) << 3) + (lane & 7)) * RS1 + (((lane >> 3) & 1) << 2)) << 2);

    int ntiles = (N + 63) >> 6;
    for (int tile = blockIdx.x; tile < ntiles; tile += gridDim.x) {
        __syncthreads();
        for (int i = 0; i < 8; i += 2) {
            int rl = w * 8 + i;
            int r0 = tile * 64 + rl, r1 = r0 + 1;
            float4 o0, o1;
            spmm_pair(rp, cols, vals, Xb, r0, r1, N, lane, o0, o1);
            uint2 st0; st0.x = packbf(o0.x, o0.y); st0.y = packbf(o0.z, o0.w);
            uint2 st1; st1.x = packbf(o1.x, o1.y); st1.y = packbf(o1.z, o1.w);
            *(uint2*)(Asu + rl * RS1 + lane * 2)       = st0;
            *(uint2*)(Asu + (rl + 1) * RS1 + lane * 2) = st1;
        }
        __syncthreads();
        float d[2][4][4];
        #pragma unroll
        for (int t = 0; t < 2; t++)
            #pragma unroll
            for (int nt = 0; nt < 4; nt++)
                #pragma unroll
                for (int j = 0; j < 4; j++) d[t][nt][j] = 0.f;
        #pragma unroll
        for (int ks = 0; ks < 8; ks++) mma_g<RS1, RS1>(d, aBase, bBase, ks);
        #pragma unroll
        for (int t = 0; t < 2; t++)
            #pragma unroll
            for (int nt = 0; nt < 4; nt++) {
                int col = nbase + nt * 8 + qc * 2;
                float b0 = biasf[col], b1 = biasf[col + 1];
                #pragma unroll
                for (int h = 0; h < 2; h++) {
                    int r = tile * 64 + mbase + t * 16 + qr + h * 8;
                    if (r < N) {
                        float s0 = sigf(fmaxf(d[t][nt][2*h]   + b0, 0.f));
                        float s1 = sigf(fmaxf(d[t][nt][2*h+1] + b1, 0.f));
                        if (addA) {
                            float2 pa = unpk(*(const unsigned*)(addA + (size_t)r * 128 + col));
                            float2 pb = unpk(*(const unsigned*)(addB + (size_t)r * 128 + col));
                            s0 = sigf((s0 + pa.x + pb.x) * 0.5f);
                            s1 = sigf((s1 + pa.y + pb.y) * 0.5f);
                        }
                        *(unsigned*)(bout + (size_t)r * 128 + col) = packbf(s0, s1);
                    }
                }
            }
    }
    // tail: independent spmm (g_from_items), paired rows, sigmoid epilogue, bf16 out
    if (t_out) {
        for (int base = blockIdx.x * 16 + w * 2; base < t_N; base += gridDim.x * 16) {
            int r0 = base, r1 = base + 1;
            float4 o0, o1;
            spmm_pair(t_rp, t_cols, t_vals, t_X, r0, r1, t_N, lane, o0, o1);
            uint2 st0; st0.x = packbf(sigf(o0.x), sigf(o0.y)); st0.y = packbf(sigf(o0.z), sigf(o0.w));
            *(uint2*)(t_out + (size_t)r0 * 128 + lane * 4) = st0;
            if (r1 < t_N) {
                uint2 st1; st1.x = packbf(sigf(o1.x), sigf(o1.y)); st1.y = packbf(sigf(o1.z), sigf(o1.w));
                *(uint2*)(t_out + (size_t)r1 * 128 + lane * 4) = st1;
            }
        }
    }
}

// ---------------- scoring with fused all_neighbors spmm (bf16 inputs) ----------------
__global__ void __launch_bounds__(256)
k_score(const int* __restrict__ gid, const int* __restrict__ iid,
        const __nv_bfloat16* __restrict__ FG, const __nv_bfloat16* __restrict__ FI,
        const int* __restrict__ rp, const int* __restrict__ cols, const float* __restrict__ vals,
        float* __restrict__ out, int B)
{
    int widx = (blockIdx.x * blockDim.x + threadIdx.x) >> 5;
    int lane = threadIdx.x & 31;
    if (widx >= B) return;
    int g = gid[widx], it = iid[widx];
    float4 ge = cvt4u(((const uint2*)(FG + (size_t)g  * 128))[lane]);
    float4 ie = cvt4u(((const uint2*)(FI + (size_t)it * 128))[lane]);
    float4 ne = spmm_row(rp, cols, vals, FG, g, lane);
    float d1 = ge.x*ie.x + ge.y*ie.y + ge.z*ie.z + ge.w*ie.w;
    float d2 = ne.x*(ge.x+ie.x) + ne.y*(ge.y+ie.y) + ne.z*(ge.z+ie.z) + ne.w*(ge.w+ie.w);
    d1 = wredsum(d1); d2 = wredsum(d2);
    if (lane == 0) { out[widx] = d1; out[B + widx] = d2; }
}

// ---------------- launch ----------------
extern "C" void kernel_launch(void* const* d_in, const int* in_sizes, int n_in,
                              void* d_out, int out_size)
{
    const int*   group_ids   = (const int*)d_in[0];
    const int*   item_ids    = (const int*)d_in[1];
    const int*   gi_rows     = (const int*)d_in[2];
    const int*   gi_cols     = (const int*)d_in[3];
    const float* gi_vals     = (const float*)d_in[4];
    const int*   gg_rows     = (const int*)d_in[5];
    const int*   gg_cols     = (const int*)d_in[6];
    const float* gg_vals     = (const float*)d_in[7];
    const float* g_feat      = (const float*)d_in[8];
    const float* i_feat      = (const float*)d_in[9];
    const float* emb_group   = (const float*)d_in[10];
    const float* emb_item    = (const float*)d_in[11];
    const float* W_w         = (const float*)d_in[12];
    const float* W_b         = (const float*)d_in[13];
    const float* red_w       = (const float*)d_in[14];
    const float* red_b       = (const float*)d_in[15];
    const float* item_fus_w  = (const float*)d_in[16];
    const float* item_fus_b  = (const float*)d_in[17];
    const float* group_fus_w = (const float*)d_in[18];
    const float* group_fus_b = (const float*)d_in[19];
    float* out = (float*)d_out;

    int B   = in_sizes[0];
    int Egi = in_sizes[2];
    int Egg = in_sizes[5];
    int NG  = in_sizes[8] / 128;  if (NG > NG_CAP) NG = NG_CAP;
    int NI  = in_sizes[9] / 128;  if (NI > NI_CAP) NI = NI_CAP;

    __nv_bfloat16 *pb_fi, *pb_fg, *pb_gfi, *pb_first, *pb_fgrp;
    int *p_rp_gi, *p_rp_gg;
    cudaGetSymbolAddress((void**)&pb_fi,    b_fi);
    cudaGetSymbolAddress((void**)&pb_fg,    b_fg);
    cudaGetSymbolAddress((void**)&pb_gfi,   b_gfi);
    cudaGetSymbolAddress((void**)&pb_first, b_first);
    cudaGetSymbolAddress((void**)&pb_fgrp,  b_fgrp);
    cudaGetSymbolAddress((void**)&p_rp_gi,  g_rp_gi);
    cudaGetSymbolAddress((void**)&p_rp_gg,  g_rp_gg);

    size_t smemS  = (size_t)(64 * RS1 + 128 * RS1) * 4 + 512;                 // ~52.7 KB (3/SM)
    size_t smemNF = (size_t)(128 * RS2 + 128 * RS1 + 128 * RS2) * 4 + 1024;   // ~167 KB (1/SM)
    cudaFuncSetAttribute(k_nf,     cudaFuncAttributeMaxDynamicSharedMemorySize, (int)smemNF);
    cudaFuncSetAttribute(k_social, cudaFuncAttributeMaxDynamicSharedMemorySize, (int)smemS);

    const int PGRID3 = 444;   // 3 blocks/SM
    int tI = (NI + 127) >> 7, tG = (NG + 127) >> 7;
    int SPLIT = (int)((long long)148 * tI / (tI + tG));
    if (SPLIT < 1) SPLIT = 1;
    if (SPLIT > 147) SPLIT = 147;

    // merged row-pointer build (both graphs in one launch)
    k_rowptr2<<<2048, 256>>>(gi_rows, Egi, NG, p_rp_gi, gg_rows, Egg, NG, p_rp_gg);

    // fused nln+fus: final_item and fus_group directly from raw inputs
    k_nf<<<148, 512, smemNF>>>(i_feat, emb_item,  item_fus_w,  item_fus_b,  pb_fi, NI,
                               g_feat, emb_group, group_fus_w, group_fus_b, pb_fg, NG,
                               red_w, red_b, SPLIT);

    // social layer 1 + tail spmm_gi (g_from_items)
    k_social<<<PGRID3, 256, smemS>>>(p_rp_gg, gg_cols, gg_vals, pb_fg, W_w, W_b,
                                     pb_first, nullptr, nullptr, NG,
                                     p_rp_gi, gi_cols, gi_vals, pb_fi, pb_gfi, NG);

    // social layer 2 fused with final_group combine
    k_social<<<PGRID3, 256, smemS>>>(p_rp_gg, gg_cols, gg_vals, pb_first, W_w, W_b,
                                     pb_fgrp, pb_gfi, pb_first, NG,
                                     nullptr, nullptr, nullptr, nullptr, nullptr, 0);

    // scoring with fused all_neighbors spmm
    k_score<<<(B + 7) / 8, 256>>>(group_ids, item_ids, pb_fgrp, pb_fi,
                                  p_rp_gg, gg_cols, gg_vals, out, B);
}